// round 5
// baseline (speedup 1.0000x reference)
#include <cuda_runtime.h>

// out[b,i,h,w] = sum_j x[b,j,h,w] - x[b,i,h,w]
// x: fp32 [16, 256, 128, 128]
//
// R5 = R4 (float4, 256-thread blocks, 4 blocks/SM) + __ldcs streaming loads.
// x is read exactly once: evict-first read lines keep L2 capacity free for
// DIRTY OUTPUT lines, so more writebacks defer past kernel end (untimed).
// R4 evidence: app traffic 6.79 TB/s vs HBM counter 6.11 TB/s => ~54 MB of
// writes already linger in L2; this change pushes that number up.

constexpr int B_DIM  = 16;
constexpr int C_DIM  = 256;
constexpr int S_DIM  = 128 * 128;        // spatial per (b,c)
constexpr int GROUPS = 32;               // channel groups per block
constexpr int CPT    = C_DIM / GROUPS;   // 8 channels per thread
constexpr int LANES  = 8;                // float4 lanes per group
constexpr int VEC    = 4;                // floats per lane (float4)
constexpr int SPB    = LANES * VEC;      // 32 spatial positions per block
constexpr int THREADS = GROUPS * LANES;  // 256

__global__ __launch_bounds__(THREADS, 4)
void neighbour_channels_kernel(const float* __restrict__ x,
                               float* __restrict__ out)
{
    __shared__ float4 red[GROUPS][LANES];

    const int lane = threadIdx.x & (LANES - 1);
    const int grp  = threadIdx.x >> 3;           // 0..31

    const int tiles_per_b = S_DIM / SPB;         // 512
    const int tile = blockIdx.x % tiles_per_b;
    const int b    = blockIdx.x / tiles_per_b;

    const long long spatial = (long long)tile * SPB + lane * VEC;
    const long long base    = (long long)b * C_DIM * S_DIM
                            + (long long)grp * CPT * S_DIM
                            + spatial;

    const float4* __restrict__ xp = (const float4*)(x + base);

    // Streaming (evict-first) loads: x lines are dead after this read, so
    // don't let them displace dirty output lines in L2.
    float4 v[CPT];
#pragma unroll
    for (int i = 0; i < CPT; ++i) {
        v[i] = __ldcs(xp + (long long)i * (S_DIM / 4));
    }

    float4 sum = make_float4(0.0f, 0.0f, 0.0f, 0.0f);
#pragma unroll
    for (int i = 0; i < CPT; ++i) {
        sum.x += v[i].x;
        sum.y += v[i].y;
        sum.z += v[i].z;
        sum.w += v[i].w;
    }

    // Cross-group reduction: 32 partials per lane.
    red[grp][lane] = sum;
    __syncthreads();

    float4 total = make_float4(0.0f, 0.0f, 0.0f, 0.0f);
#pragma unroll
    for (int g = 0; g < GROUPS; ++g) {
        float4 p = red[g][lane];
        total.x += p.x;
        total.y += p.y;
        total.z += p.z;
        total.w += p.w;
    }

    // Write out = total - x from registers (default writeback stores: dirty
    // lines may linger in L2 and flush after the timed region).
    float4* __restrict__ op = (float4*)(out + base);
#pragma unroll
    for (int i = 0; i < CPT; ++i) {
        float4 o;
        o.x = total.x - v[i].x;
        o.y = total.y - v[i].y;
        o.z = total.z - v[i].z;
        o.w = total.w - v[i].w;
        op[(long long)i * (S_DIM / 4)] = o;
    }
}

extern "C" void kernel_launch(void* const* d_in, const int* in_sizes, int n_in,
                              void* d_out, int out_size)
{
    const float* x = (const float*)d_in[0];
    float* out = (float*)d_out;

    const int grid = B_DIM * (S_DIM / SPB);  // 16 * 512 = 8192 blocks
    neighbour_channels_kernel<<<grid, THREADS>>>(x, out);
}